// round 12
// baseline (speedup 1.0000x reference)
#include <cuda_runtime.h>

#define BB 256
#define SS 2048
#define KK 64
#define PF 8      // score prefetch depth (steps)
#define HALF 1024 // steps per half-chain

// Scratch (no allocations allowed in kernel_launch)
__device__ float  g_M[KK * KK];   // exp(transition)
__device__ float  g_Af[BB * KK];  // forward alpha at t=HALF-1 (scaled)
__device__ float  g_Bb[BB * KK];  // backward beta' at t=HALF-1 (scaled)
__device__ int    g_cf[BB];       // forward exponent offset (log2 units)
__device__ int    g_cb[BB];       // backward exponent offset
__device__ double g_logZ[BB];
__device__ double g_gold[BB];

// ---------- packed f32x2 helpers (Blackwell FFMA2 path, PTX-only) ----------
__device__ __forceinline__ unsigned long long fma2(unsigned long long a,
                                                   unsigned long long b,
                                                   unsigned long long c) {
    unsigned long long d;
    asm("fma.rn.f32x2 %0, %1, %2, %3;" : "=l"(d) : "l"(a), "l"(b), "l"(c));
    return d;
}
__device__ __forceinline__ unsigned long long add2(unsigned long long a,
                                                   unsigned long long b) {
    unsigned long long d;
    asm("add.rn.f32x2 %0, %1, %2;" : "=l"(d) : "l"(a), "l"(b));
    return d;
}
__device__ __forceinline__ float2 unpack2(unsigned long long v) {
    float2 r;
    asm("mov.b64 {%0, %1}, %2;" : "=f"(r.x), "=f"(r.y) : "l"(v));
    return r;
}
__device__ __forceinline__ unsigned long long pack2(float lo, float hi) {
    unsigned long long r;
    asm("mov.b64 %0, {%1, %2};" : "=l"(r) : "f"(lo), "f"(hi));
    return r;
}
__device__ __forceinline__ float warp_sum(float v) {
#pragma unroll
    for (int o = 16; o > 0; o >>= 1)
        v += __shfl_xor_sync(0xffffffffu, v, o);
    return v;
}
// 64-thread group barrier (named, ids 1/2) — decouples the two chains.
__device__ __forceinline__ void group_bar(int id) {
    asm volatile("bar.sync %0, 64;" :: "r"(id) : "memory");
}

// 64-wide matvec partial: sum_i A[i]*Mreg[i] (paired), 4 accumulator chains.
__device__ __forceinline__ float matvec64(const ulonglong2* e4,
                                          const unsigned long long* Mreg) {
    unsigned long long a0 = 0ull, a1 = 0ull, a2 = 0ull, a3 = 0ull;
#pragma unroll
    for (int q = 0; q < 16; q += 2) {
        ulonglong2 ea = e4[q];
        ulonglong2 eb = e4[q + 1];
        a0 = fma2(ea.x, Mreg[2 * q + 0], a0);
        a1 = fma2(ea.y, Mreg[2 * q + 1], a1);
        a2 = fma2(eb.x, Mreg[2 * q + 2], a2);
        a3 = fma2(eb.y, Mreg[2 * q + 3], a3);
    }
    a0 = add2(a0, a1);
    a2 = add2(a2, a3);
    a0 = add2(a0, a2);
    float2 ac = unpack2(a0);
    return ac.x + ac.y;
}

// ---------- kernels ----------
__global__ void init_kernel(const float* __restrict__ T) {
    int i = blockIdx.x * blockDim.x + threadIdx.x;
    if (i < KK * KK) g_M[i] = expf(T[i]);
}

// 256 CTAs x 128 threads. Chain 0 (warps 0/1, SMSP 0/1) = forward half of
// batch b; chain 1 (warps 2/3, SMSP 2/3) = backward half of the SAME batch.
// Each chain syncs with its OWN 2-warp named barrier (no 4-warp coupling).
// Steps v = 1..HALF-1 exactly (break restored: no double-counted rows).
__global__ __launch_bounds__(128) void main_kernel(
    const float* __restrict__ scores,
    const float* __restrict__ source,
    const float* __restrict__ sink) {
    __shared__ __align__(16) float sA[2][2][KK];  // [chain][parity][state]

    const int chain = threadIdx.x >> 6;   // 0 = forward, 1 = backward
    const int j     = threadIdx.x & 63;   // state owned by this thread
    const int bid   = chain + 1;          // named barrier id
    const int b     = blockIdx.x;
    const float* sc = scores + (size_t)b * (SS * KK);
    const bool fwd  = (chain == 0);

    const float LOG2E = 1.44269504088896340736f;

    // M slice in registers: forward = column j (stride KK), backward = row j.
    const int m0 = fwd ? j : j * KK;
    const int ms = fwd ? KK : 1;
    unsigned long long Mreg[32];
#pragma unroll
    for (int p = 0; p < 32; ++p)
        Mreg[p] = pack2(g_M[m0 + (2 * p) * ms], g_M[m0 + (2 * p + 1) * ms]);

    const int t0  = fwd ? 0 : SS - 1;
    const int sgn = fwd ? 1 : -1;

    // Score prefetch ring + rolling refill pointer (row t0+sgn*(v+PF) at step v).
    float s_ring[PF];
#pragma unroll
    for (int k = 0; k < PF; ++k)
        s_ring[k] = __ldg(&sc[(size_t)(t0 + sgn * (1 + k)) * KK + j]);
    const float* pp = sc + (size_t)(t0 + sgn * (1 + PF)) * KK + j;
    const ptrdiff_t pstep = (ptrdiff_t)sgn * KK;

    // Init: fwd A_0 = exp(source + s_0); bwd Bv = exp(sink + s_{2047}).
    float bnd  = fwd ? __ldg(&source[j]) : __ldg(&sink[j]);
    float Acur = exp2f((bnd + __ldg(&sc[(size_t)t0 * KK + j])) * LOG2E);
    int c = 0;
    sA[chain][0][j] = Acur;
    group_bar(bid);

#pragma unroll 1
    for (int base = 1; base < HALF; base += PF) {
#pragma unroll
        for (int k = 0; k < PF; ++k) {
            const int v   = base + k;
            if (v >= HALF) break;          // run v = 1..HALF-1 exactly
            const int par = v & 1;

            // es for this step (row loaded PF steps ago); rolling refill.
            float es = exp2f(s_ring[k] * LOG2E);
            s_ring[k] = __ldg(pp);
            pp += pstep;

            // Consistent power-of-2 rescale from exponent of prev[0]
            // (same shared word on every thread of the chain).
            float A0v = sA[chain][par ^ 1][0];
            int e0 = (int)((__float_as_uint(A0v) >> 23) & 0xFF);
            float scale = __uint_as_float((unsigned)(254 - e0) << 23);
            c += e0 - 127;

            float sum = matvec64(
                reinterpret_cast<const ulonglong2*>(sA[chain][par ^ 1]), Mreg);
            Acur = sum * (es * scale);
            sA[chain][par][j] = Acur;
            group_bar(bid);
        }
    }
    // Loop ran v = 1..1023; last write was to parity 1.

    if (fwd) {
        g_Af[b * KK + j] = Acur;          // alpha_{1023}, scaled 2^-c
        if (j == 0) g_cf[b] = c;
    } else {
        // beta'_{1023} = M * Bv_{1024} (no es), one extra renormalized matvec.
        float B0v = sA[chain][1][0];
        int e0 = (int)((__float_as_uint(B0v) >> 23) & 0xFF);
        float scale = __uint_as_float((unsigned)(254 - e0) << 23);
        c += e0 - 127;
        float sum = matvec64(
            reinterpret_cast<const ulonglong2*>(sA[chain][1]), Mreg);
        g_Bb[b * KK + j] = sum * scale;   // beta'_{1023}, scaled 2^-c
        if (j == 0) g_cb[b] = c;
    }
}

// logZ_b = log(sum_j Af[b][j]*Bb[b][j]) + (cf+cb)*ln2
__global__ __launch_bounds__(64) void combine_kernel() {
    __shared__ float sRed[2];
    const int b = blockIdx.x, j = threadIdx.x;
    float v = g_Af[b * KK + j] * g_Bb[b * KK + j];
    float ws = warp_sum(v);
    if ((j & 31) == 0) sRed[j >> 5] = ws;
    __syncthreads();
    if (j == 0) {
        float tot = sRed[0] + sRed[1];
        g_logZ[b] = ((double)log2f(tot) + (double)(g_cf[b] + g_cb[b])) *
                    0.69314718055994530942;
    }
}

__global__ __launch_bounds__(256) void gold_kernel(
    const float* __restrict__ scores,
    const int* __restrict__ states,
    const float* __restrict__ T,
    const float* __restrict__ source,
    const float* __restrict__ sink) {
    __shared__ float red[256];
    const int b = blockIdx.x, tid = threadIdx.x;
    const int*   st = states + (size_t)b * SS;
    const float* sc = scores + (size_t)b * (SS * KK);

    float acc = 0.f;
    for (int t = tid; t < SS; t += 256) {
        int s0 = __ldg(&st[t]);
        acc += __ldg(&sc[t * KK + s0]);
        if (t + 1 < SS) acc += __ldg(&T[s0 * KK + __ldg(&st[t + 1])]);
    }
    red[tid] = acc;
    __syncthreads();
#pragma unroll
    for (int off = 128; off > 0; off >>= 1) {
        if (tid < off) red[tid] += red[tid + off];
        __syncthreads();
    }
    if (tid == 0)
        g_gold[b] = (double)red[0] + (double)__ldg(&source[__ldg(&st[0])]) +
                    (double)__ldg(&sink[__ldg(&st[SS - 1])]);
}

__global__ __launch_bounds__(256) void finalize_kernel(float* __restrict__ out) {
    __shared__ double red[256];
    const int tid = threadIdx.x;
    red[tid] = g_logZ[tid] - g_gold[tid];
    __syncthreads();
#pragma unroll
    for (int off = 128; off > 0; off >>= 1) {
        if (tid < off) red[tid] += red[tid + off];
        __syncthreads();
    }
    if (tid == 0) *out = (float)(red[0] * (1.0 / BB));
}

extern "C" void kernel_launch(void* const* d_in, const int* in_sizes, int n_in,
                              void* d_out, int out_size) {
    const float* scores = (const float*)d_in[0];   // [B,S,K] f32
    const int*   states = (const int*)d_in[1];     // [B,S] i32
    const float* T      = (const float*)d_in[2];   // [K,K] f32
    const float* source = (const float*)d_in[3];   // [K] f32
    const float* sink   = (const float*)d_in[4];   // [K] f32
    float* out = (float*)d_out;

    init_kernel<<<16, 256>>>(T);
    main_kernel<<<BB, 128>>>(scores, source, sink);
    gold_kernel<<<BB, 256>>>(scores, states, T, source, sink);
    combine_kernel<<<BB, 64>>>();
    finalize_kernel<<<1, 256>>>(out);
}

// round 13
// speedup vs baseline: 1.6252x; 1.6252x over previous
#include <cuda_runtime.h>

#define BB 256
#define SS 2048
#define KK 64
#define PF 8      // score prefetch depth (steps)
#define HALF 1024 // steps per half-chain

// Scratch (no allocations allowed in kernel_launch)
__device__ float  g_M[KK * KK];   // exp(transition)
__device__ float  g_Af[BB * KK];  // forward alpha at t=HALF-1 (scaled)
__device__ float  g_Bb[BB * KK];  // backward beta' at t=HALF-1 (scaled)
__device__ int    g_cf[BB];       // forward exponent offset (log2 units)
__device__ int    g_cb[BB];       // backward exponent offset
__device__ double g_logZ[BB];
__device__ double g_gold[BB];

// ---------- packed f32x2 helpers (Blackwell FFMA2 path, PTX-only) ----------
__device__ __forceinline__ unsigned long long fma2(unsigned long long a,
                                                   unsigned long long b,
                                                   unsigned long long c) {
    unsigned long long d;
    asm("fma.rn.f32x2 %0, %1, %2, %3;" : "=l"(d) : "l"(a), "l"(b), "l"(c));
    return d;
}
__device__ __forceinline__ unsigned long long add2(unsigned long long a,
                                                   unsigned long long b) {
    unsigned long long d;
    asm("add.rn.f32x2 %0, %1, %2;" : "=l"(d) : "l"(a), "l"(b));
    return d;
}
__device__ __forceinline__ float2 unpack2(unsigned long long v) {
    float2 r;
    asm("mov.b64 {%0, %1}, %2;" : "=f"(r.x), "=f"(r.y) : "l"(v));
    return r;
}
__device__ __forceinline__ unsigned long long pack2(float lo, float hi) {
    unsigned long long r;
    asm("mov.b64 %0, {%1, %2};" : "=l"(r) : "f"(lo), "f"(hi));
    return r;
}
__device__ __forceinline__ float warp_sum(float v) {
#pragma unroll
    for (int o = 16; o > 0; o >>= 1)
        v += __shfl_xor_sync(0xffffffffu, v, o);
    return v;
}

// 64-wide matvec partial: sum_i A[i]*Mreg[i] (paired), 4 accumulator chains.
__device__ __forceinline__ float matvec64(const ulonglong2* e4,
                                          const unsigned long long* Mreg) {
    unsigned long long a0 = 0ull, a1 = 0ull, a2 = 0ull, a3 = 0ull;
#pragma unroll
    for (int q = 0; q < 16; q += 2) {
        ulonglong2 ea = e4[q];
        ulonglong2 eb = e4[q + 1];
        a0 = fma2(ea.x, Mreg[2 * q + 0], a0);
        a1 = fma2(ea.y, Mreg[2 * q + 1], a1);
        a2 = fma2(eb.x, Mreg[2 * q + 2], a2);
        a3 = fma2(eb.y, Mreg[2 * q + 3], a3);
    }
    a0 = add2(a0, a1);
    a2 = add2(a2, a3);
    a0 = add2(a0, a2);
    float2 ac = unpack2(a0);
    return ac.x + ac.y;
}

// Power-of-2 renormalizer from a shared word (bit-identical on all threads).
__device__ __forceinline__ float renorm(float head, int& c) {
    int e0 = (int)((__float_as_uint(head) >> 23) & 0xFF);
    c += e0 - 127;
    return __uint_as_float((unsigned)(254 - e0) << 23);
}

// ---------- kernels ----------
__global__ void init_kernel(const float* __restrict__ T) {
    int i = blockIdx.x * blockDim.x + threadIdx.x;
    if (i < KK * KK) g_M[i] = expf(T[i]);
}

// 128 CTAs x 128 threads (guaranteed 1 CTA/SM, all 4 SMSPs, no stacking).
// Group 0 (warps 0/1) = FORWARD halves of batches 2b, 2b+1; group 1
// (warps 2/3) = BACKWARD halves of the same two batches. Both batches in a
// group share the SAME M registers (fwd: column j; bwd: row j), so the dual
// matvec costs only FMA issue, amortizing the barrier + serial latency over
// two chain-steps. One block-wide __syncthreads per step (named barriers are
// catastrophically slow with concurrent groups — measured R11).
__global__ __launch_bounds__(128) void main_kernel(
    const float* __restrict__ scores,
    const float* __restrict__ source,
    const float* __restrict__ sink) {
    __shared__ __align__(16) float sA[2][2][2][KK];  // [grp][batch][parity][state]

    const int grp = threadIdx.x >> 6;     // 0 = forward, 1 = backward
    const int j   = threadIdx.x & 63;     // state owned by this thread
    const bool fwd = (grp == 0);
    const int b0  = blockIdx.x << 1;      // batches b0, b0+1
    const float* sc0 = scores + (size_t)b0 * (SS * KK);
    const float* sc1 = sc0 + (size_t)SS * KK;

    const float LOG2E = 1.44269504088896340736f;

    // M slice in registers (shared by both batches of this group):
    // forward = column j (stride KK), backward = row j (stride 1).
    const int m0 = fwd ? j : j * KK;
    const int ms = fwd ? KK : 1;
    unsigned long long Mreg[32];
#pragma unroll
    for (int p = 0; p < 32; ++p)
        Mreg[p] = pack2(g_M[m0 + (2 * p) * ms], g_M[m0 + (2 * p + 1) * ms]);

    const int t0  = fwd ? 0 : SS - 1;
    const int sgn = fwd ? 1 : -1;

    // Score prefetch rings + rolling refill pointers.
    float ring0[PF], ring1[PF];
#pragma unroll
    for (int k = 0; k < PF; ++k) {
        ring0[k] = __ldg(&sc0[(size_t)(t0 + sgn * (1 + k)) * KK + j]);
        ring1[k] = __ldg(&sc1[(size_t)(t0 + sgn * (1 + k)) * KK + j]);
    }
    const ptrdiff_t pstep = (ptrdiff_t)sgn * KK;
    const float* pp0 = sc0 + (size_t)(t0 + sgn * (1 + PF)) * KK + j;
    const float* pp1 = sc1 + (size_t)(t0 + sgn * (1 + PF)) * KK + j;

    // Init: fwd A_0 = exp(source + s_0); bwd Bv = exp(sink + s_{2047}).
    float bnd = fwd ? __ldg(&source[j]) : __ldg(&sink[j]);
    float A0 = exp2f((bnd + __ldg(&sc0[(size_t)t0 * KK + j])) * LOG2E);
    float A1 = exp2f((bnd + __ldg(&sc1[(size_t)t0 * KK + j])) * LOG2E);
    int c0 = 0, c1 = 0;
    sA[grp][0][0][j] = A0;
    sA[grp][1][0][j] = A1;
    __syncthreads();

#pragma unroll 1
    for (int base = 1; base < HALF; base += PF) {
#pragma unroll
        for (int k = 0; k < PF; ++k) {
            const int v = base + k;
            if (v >= HALF) break;          // run v = 1..HALF-1 exactly
            const int par = v & 1;

            // es for this step (rows loaded PF steps ago); rolling refills.
            float es0 = exp2f(ring0[k] * LOG2E);
            float es1 = exp2f(ring1[k] * LOG2E);
            ring0[k] = __ldg(pp0); pp0 += pstep;
            ring1[k] = __ldg(pp1); pp1 += pstep;

            // Per-batch consistent power-of-2 rescale.
            float sc_a = renorm(sA[grp][0][par ^ 1][0], c0);
            float sc_b = renorm(sA[grp][1][par ^ 1][0], c1);

            float sum0 = matvec64(
                reinterpret_cast<const ulonglong2*>(sA[grp][0][par ^ 1]), Mreg);
            float sum1 = matvec64(
                reinterpret_cast<const ulonglong2*>(sA[grp][1][par ^ 1]), Mreg);

            A0 = sum0 * (es0 * sc_a);
            A1 = sum1 * (es1 * sc_b);
            sA[grp][0][par][j] = A0;
            sA[grp][1][par][j] = A1;
            __syncthreads();
        }
    }
    // Loop ran v = 1..1023; last write was to parity 1.

    if (fwd) {
        g_Af[(b0 + 0) * KK + j] = A0;      // alpha_{1023}, scaled 2^-c
        g_Af[(b0 + 1) * KK + j] = A1;
        if (j == 0) { g_cf[b0] = c0; g_cf[b0 + 1] = c1; }
    } else {
        // beta'_{1023} = M * Bv_{1024} (no es), one extra renormalized matvec.
        float sc_a = renorm(sA[1][0][1][0], c0);
        float sc_b = renorm(sA[1][1][1][0], c1);
        float sum0 = matvec64(
            reinterpret_cast<const ulonglong2*>(sA[1][0][1]), Mreg);
        float sum1 = matvec64(
            reinterpret_cast<const ulonglong2*>(sA[1][1][1]), Mreg);
        g_Bb[(b0 + 0) * KK + j] = sum0 * sc_a;
        g_Bb[(b0 + 1) * KK + j] = sum1 * sc_b;
        if (j == 0) { g_cb[b0] = c0; g_cb[b0 + 1] = c1; }
    }
}

// logZ_b = log(sum_j Af[b][j]*Bb[b][j]) + (cf+cb)*ln2
__global__ __launch_bounds__(64) void combine_kernel() {
    __shared__ float sRed[2];
    const int b = blockIdx.x, j = threadIdx.x;
    float v = g_Af[b * KK + j] * g_Bb[b * KK + j];
    float ws = warp_sum(v);
    if ((j & 31) == 0) sRed[j >> 5] = ws;
    __syncthreads();
    if (j == 0) {
        float tot = sRed[0] + sRed[1];
        g_logZ[b] = ((double)log2f(tot) + (double)(g_cf[b] + g_cb[b])) *
                    0.69314718055994530942;
    }
}

__global__ __launch_bounds__(256) void gold_kernel(
    const float* __restrict__ scores,
    const int* __restrict__ states,
    const float* __restrict__ T,
    const float* __restrict__ source,
    const float* __restrict__ sink) {
    __shared__ float red[256];
    const int b = blockIdx.x, tid = threadIdx.x;
    const int*   st = states + (size_t)b * SS;
    const float* sc = scores + (size_t)b * (SS * KK);

    float acc = 0.f;
    for (int t = tid; t < SS; t += 256) {
        int s0 = __ldg(&st[t]);
        acc += __ldg(&sc[t * KK + s0]);
        if (t + 1 < SS) acc += __ldg(&T[s0 * KK + __ldg(&st[t + 1])]);
    }
    red[tid] = acc;
    __syncthreads();
#pragma unroll
    for (int off = 128; off > 0; off >>= 1) {
        if (tid < off) red[tid] += red[tid + off];
        __syncthreads();
    }
    if (tid == 0)
        g_gold[b] = (double)red[0] + (double)__ldg(&source[__ldg(&st[0])]) +
                    (double)__ldg(&sink[__ldg(&st[SS - 1])]);
}

__global__ __launch_bounds__(256) void finalize_kernel(float* __restrict__ out) {
    __shared__ double red[256];
    const int tid = threadIdx.x;
    red[tid] = g_logZ[tid] - g_gold[tid];
    __syncthreads();
#pragma unroll
    for (int off = 128; off > 0; off >>= 1) {
        if (tid < off) red[tid] += red[tid + off];
        __syncthreads();
    }
    if (tid == 0) *out = (float)(red[0] * (1.0 / BB));
}

extern "C" void kernel_launch(void* const* d_in, const int* in_sizes, int n_in,
                              void* d_out, int out_size) {
    const float* scores = (const float*)d_in[0];   // [B,S,K] f32
    const int*   states = (const int*)d_in[1];     // [B,S] i32
    const float* T      = (const float*)d_in[2];   // [K,K] f32
    const float* source = (const float*)d_in[3];   // [K] f32
    const float* sink   = (const float*)d_in[4];   // [K] f32
    float* out = (float*)d_out;

    init_kernel<<<16, 256>>>(T);
    main_kernel<<<BB / 2, 128>>>(scores, source, sink);
    gold_kernel<<<BB, 256>>>(scores, states, T, source, sink);
    combine_kernel<<<BB, 64>>>();
    finalize_kernel<<<1, 256>>>(out);
}